// round 2
// baseline (speedup 1.0000x reference)
#include <cuda_runtime.h>
#include <cuda_bf16.h>
#include <stdint.h>

#define COLS 1024
#define CPC 8
#define NCELLS 8192            // COLS * CPC
#define THRESH 13.0f
#define PERM_CONN 0.5f

// out layout: [0:8192) new_active, [8192:16384) new_predictive,
//             [16384] anomaly, [16385:16385+64M) new_segment_weights
//
// Fully fused: each block recomputes new_active into smem (cheap, L2-fed),
// then streams one 32KB weight row: matvec accumulate + permanence update.
// prev_has flag is algebraically removed: prev is binary >= 0, so
// (sum(prev)>0 && prev[r]!=0) == (prev[r]!=0), and when prev[r]==0 the
// "updated" branch equals W anyway (clip identity on [0,1)).
__global__ __launch_bounds__(256) void tm_fused_kernel(
    const float* __restrict__ active_columns,
    const float* __restrict__ W,
    const float* __restrict__ predictive_cells,
    const float* __restrict__ prev_active,
    float* __restrict__ out) {

    __shared__ float a_s[NCELLS];       // 32 KB: new_active, block-local
    __shared__ float s_red[8];

    const int t = threadIdx.x;
    const int r = blockIdx.x;

    // ---- recompute new_active into smem (all blocks) ----
    const float4* __restrict__ p4 = reinterpret_cast<const float4*>(predictive_cells);
    float4* a_s4 = reinterpret_cast<float4*>(a_s);

    float na_loc = 0.f, np_loc = 0.f;
#pragma unroll
    for (int k = 0; k < 4; k++) {
        int c = t + k * 256;            // column id
        float4 p0 = p4[2 * c];
        float4 p1 = p4[2 * c + 1];
        float psum = p0.x + p0.y + p0.z + p0.w + p1.x + p1.y + p1.z + p1.w;
        bool hp = psum > 0.f;
        bool am = active_columns[c] > 0.f;
        float4 v0, v1;
        if (hp) { v0 = p0; v1 = p1; }
        else    { v0 = make_float4(1.f,1.f,1.f,1.f); v1 = v0; }
        if (!am){ v0 = make_float4(0.f,0.f,0.f,0.f); v1 = v0; }
        a_s4[2 * c]     = v0;
        a_s4[2 * c + 1] = v1;
        na_loc += am ? 1.f : 0.f;
        np_loc += (am && hp) ? 1.f : 0.f;
    }
    __syncthreads();

    // ---- block 0 only: anomaly + publish new_active to gmem ----
    if (r == 0) {
        float na = na_loc, np = np_loc;
#pragma unroll
        for (int off = 16; off > 0; off >>= 1) {
            na += __shfl_down_sync(0xFFFFFFFFu, na, off);
            np += __shfl_down_sync(0xFFFFFFFFu, np, off);
        }
        __shared__ float s_na[8], s_np[8];
        int w = t >> 5, l = t & 31;
        if (l == 0) { s_na[w] = na; s_np[w] = np; }
        __syncthreads();
        if (t == 0) {
            float tna = 0.f, tnp = 0.f;
#pragma unroll
            for (int i = 0; i < 8; i++) { tna += s_na[i]; tnp += s_np[i]; }
            out[2 * NCELLS] = 1.0f - tnp / fmaxf(tna, 1.0f);   // anomaly
        }
        // new_active -> gmem
        float4* oa4 = reinterpret_cast<float4*>(out);
#pragma unroll
        for (int k = 0; k < 8; k++) {
            int idx = t + k * 256;
            oa4[idx] = a_s4[idx];
        }
    }

    // ---- stream one weight row: matvec + permanence update ----
    const float4* __restrict__ wrow =
        reinterpret_cast<const float4*>(W + (size_t)r * NCELLS);
    float* __restrict__ orow = out + 2 * NCELLS + 1 + (size_t)r * NCELLS;

    const float p = prev_active[r];     // gate removed (see header comment)
    float acc = 0.f;

    if (p != 0.f) {
#pragma unroll
        for (int i = 0; i < 8; i++) {
            int idx = t + i * 256;
            float4 w4 = wrow[idx];
            float4 a4 = a_s4[idx];
            acc += (w4.x >= PERM_CONN ? a4.x : 0.f)
                 + (w4.y >= PERM_CONN ? a4.y : 0.f)
                 + (w4.z >= PERM_CONN ? a4.z : 0.f)
                 + (w4.w >= PERM_CONN ? a4.w : 0.f);
            float ox = fminf(fmaxf(w4.x + (0.1f * a4.x - 0.01f * (1.f - a4.x)) * p, 0.f), 1.f);
            float oy = fminf(fmaxf(w4.y + (0.1f * a4.y - 0.01f * (1.f - a4.y)) * p, 0.f), 1.f);
            float oz = fminf(fmaxf(w4.z + (0.1f * a4.z - 0.01f * (1.f - a4.z)) * p, 0.f), 1.f);
            float ow = fminf(fmaxf(w4.w + (0.1f * a4.w - 0.01f * (1.f - a4.w)) * p, 0.f), 1.f);
            int j = idx * 4;
            orow[j + 0] = ox;
            orow[j + 1] = oy;
            orow[j + 2] = oz;
            orow[j + 3] = ow;
        }
    } else {
#pragma unroll
        for (int i = 0; i < 8; i++) {
            int idx = t + i * 256;
            float4 w4 = wrow[idx];
            float4 a4 = a_s4[idx];
            acc += (w4.x >= PERM_CONN ? a4.x : 0.f)
                 + (w4.y >= PERM_CONN ? a4.y : 0.f)
                 + (w4.z >= PERM_CONN ? a4.z : 0.f)
                 + (w4.w >= PERM_CONN ? a4.w : 0.f);
            int j = idx * 4;
            orow[j + 0] = w4.x;
            orow[j + 1] = w4.y;
            orow[j + 2] = w4.z;
            orow[j + 3] = w4.w;
        }
    }

    // ---- block reduce acc -> new_predictive[r] ----
#pragma unroll
    for (int off = 16; off > 0; off >>= 1)
        acc += __shfl_down_sync(0xFFFFFFFFu, acc, off);
    int w = t >> 5, l = t & 31;
    if (l == 0) s_red[w] = acc;
    __syncthreads();
    if (t == 0) {
        float s = 0.f;
#pragma unroll
        for (int i = 0; i < 8; i++) s += s_red[i];
        out[NCELLS + r] = (s >= THRESH) ? 1.0f : 0.0f;
    }
}

extern "C" void kernel_launch(void* const* d_in, const int* in_sizes, int n_in,
                              void* d_out, int out_size) {
    const float* active_columns  = (const float*)d_in[0];
    const float* segment_weights = (const float*)d_in[1];
    const float* predictive      = (const float*)d_in[2];
    const float* prev_active     = (const float*)d_in[3];
    float* out = (float*)d_out;

    tm_fused_kernel<<<NCELLS, 256>>>(active_columns, segment_weights,
                                     predictive, prev_active, out);
}

// round 3
// speedup vs baseline: 1.1813x; 1.1813x over previous
#include <cuda_runtime.h>
#include <cuda_bf16.h>
#include <stdint.h>

#define COLS 1024
#define CPC 8
#define NCELLS 8192            // COLS * CPC
#define THRESH 13.0f
#define PERM_CONN 0.5f

// out layout: [0:8192) new_active, [8192:16384) new_predictive,
//             [16384] anomaly, [16385:16385+64M) new_segment_weights
//
// prev_has gate is algebraically removed: prev_active is binary >= 0, so
// (sum(prev)>0 && prev[r]!=0) == (prev[r]!=0), and when prev[r]==0 the
// updated row equals W anyway (clip is identity on [0,1)).

// ---------------------------------------------------------------------------
// K1: new_active only. 4 blocks x 256 threads = 1024 threads, one per column.
// Pure float4 traffic, ~2us.
// ---------------------------------------------------------------------------
__global__ __launch_bounds__(256) void tm_active_kernel(
    const float* __restrict__ active_columns,
    const float* __restrict__ predictive_cells,
    float* __restrict__ out) {
    int c = blockIdx.x * 256 + threadIdx.x;   // column id 0..1023
    const float4* __restrict__ p4 = reinterpret_cast<const float4*>(predictive_cells);
    float4* __restrict__ o4 = reinterpret_cast<float4*>(out);

    float4 p0 = p4[2 * c];
    float4 p1 = p4[2 * c + 1];
    float psum = p0.x + p0.y + p0.z + p0.w + p1.x + p1.y + p1.z + p1.w;
    bool hp = psum > 0.f;
    bool am = active_columns[c] > 0.f;

    float4 v0, v1;
    if (hp) { v0 = p0; v1 = p1; }
    else    { v0 = make_float4(1.f, 1.f, 1.f, 1.f); v1 = v0; }
    if (!am) { v0 = make_float4(0.f, 0.f, 0.f, 0.f); v1 = v0; }
    o4[2 * c]     = v0;
    o4[2 * c + 1] = v1;
}

// ---------------------------------------------------------------------------
// K2: 8193 blocks. Blocks 0..8191: fused matvec + permanence update, one
// 32KB row each, streaming loads/stores with .cs (no-reuse) hints.
// Block 8192: anomaly (runs concurrently, hidden under the stream).
// ---------------------------------------------------------------------------
__global__ __launch_bounds__(256) void tm_row_kernel(
    const float* __restrict__ W,
    const float* __restrict__ active_columns,
    const float* __restrict__ predictive_cells,
    const float* __restrict__ prev_active,
    float* __restrict__ out) {
    const int r = blockIdx.x;
    const int t = threadIdx.x;

    if (r == NCELLS) {
        // ---- anomaly block ----
        const float4* __restrict__ p4 =
            reinterpret_cast<const float4*>(predictive_cells);
        float na = 0.f, np = 0.f;
#pragma unroll
        for (int k = 0; k < 4; k++) {
            int c = t + k * 256;
            float4 p0 = p4[2 * c];
            float4 p1 = p4[2 * c + 1];
            float psum = p0.x + p0.y + p0.z + p0.w + p1.x + p1.y + p1.z + p1.w;
            bool hp = psum > 0.f;
            bool am = active_columns[c] > 0.f;
            na += am ? 1.f : 0.f;
            np += (am && hp) ? 1.f : 0.f;
        }
#pragma unroll
        for (int off = 16; off > 0; off >>= 1) {
            na += __shfl_down_sync(0xFFFFFFFFu, na, off);
            np += __shfl_down_sync(0xFFFFFFFFu, np, off);
        }
        __shared__ float s_na[8], s_np[8];
        int w = t >> 5, l = t & 31;
        if (l == 0) { s_na[w] = na; s_np[w] = np; }
        __syncthreads();
        if (t == 0) {
            float tna = 0.f, tnp = 0.f;
#pragma unroll
            for (int i = 0; i < 8; i++) { tna += s_na[i]; tnp += s_np[i]; }
            out[2 * NCELLS] = 1.0f - tnp / fmaxf(tna, 1.0f);
        }
        return;
    }

    // ---- streaming row block ----
    const float* __restrict__ a = out;                 // new_active (from K1)
    const float4* __restrict__ wrow =
        reinterpret_cast<const float4*>(W + (size_t)r * NCELLS);
    const float4* __restrict__ a4p = reinterpret_cast<const float4*>(a);
    float* __restrict__ orow = out + 2 * NCELLS + 1 + (size_t)r * NCELLS;

    const float p = prev_active[r];
    float acc = 0.f;

    if (p != 0.f) {
#pragma unroll
        for (int i = 0; i < 8; i++) {
            int idx = t + i * 256;
            float4 w4 = __ldcs(&wrow[idx]);
            float4 a4 = a4p[idx];
            acc += (w4.x >= PERM_CONN ? a4.x : 0.f)
                 + (w4.y >= PERM_CONN ? a4.y : 0.f)
                 + (w4.z >= PERM_CONN ? a4.z : 0.f)
                 + (w4.w >= PERM_CONN ? a4.w : 0.f);
            float ox = fminf(fmaxf(w4.x + (0.1f * a4.x - 0.01f * (1.f - a4.x)) * p, 0.f), 1.f);
            float oy = fminf(fmaxf(w4.y + (0.1f * a4.y - 0.01f * (1.f - a4.y)) * p, 0.f), 1.f);
            float oz = fminf(fmaxf(w4.z + (0.1f * a4.z - 0.01f * (1.f - a4.z)) * p, 0.f), 1.f);
            float ow = fminf(fmaxf(w4.w + (0.1f * a4.w - 0.01f * (1.f - a4.w)) * p, 0.f), 1.f);
            int j = idx * 4;
            __stcs(&orow[j + 0], ox);
            __stcs(&orow[j + 1], oy);
            __stcs(&orow[j + 2], oz);
            __stcs(&orow[j + 3], ow);
        }
    } else {
#pragma unroll
        for (int i = 0; i < 8; i++) {
            int idx = t + i * 256;
            float4 w4 = __ldcs(&wrow[idx]);
            float4 a4 = a4p[idx];
            acc += (w4.x >= PERM_CONN ? a4.x : 0.f)
                 + (w4.y >= PERM_CONN ? a4.y : 0.f)
                 + (w4.z >= PERM_CONN ? a4.z : 0.f)
                 + (w4.w >= PERM_CONN ? a4.w : 0.f);
            int j = idx * 4;
            __stcs(&orow[j + 0], w4.x);
            __stcs(&orow[j + 1], w4.y);
            __stcs(&orow[j + 2], w4.z);
            __stcs(&orow[j + 3], w4.w);
        }
    }

    // ---- block reduce acc -> new_predictive[r] ----
#pragma unroll
    for (int off = 16; off > 0; off >>= 1)
        acc += __shfl_down_sync(0xFFFFFFFFu, acc, off);
    __shared__ float s_red[8];
    int w = t >> 5, l = t & 31;
    if (l == 0) s_red[w] = acc;
    __syncthreads();
    if (t == 0) {
        float s = 0.f;
#pragma unroll
        for (int i = 0; i < 8; i++) s += s_red[i];
        out[NCELLS + r] = (s >= THRESH) ? 1.0f : 0.0f;
    }
}

extern "C" void kernel_launch(void* const* d_in, const int* in_sizes, int n_in,
                              void* d_out, int out_size) {
    const float* active_columns  = (const float*)d_in[0];
    const float* segment_weights = (const float*)d_in[1];
    const float* predictive      = (const float*)d_in[2];
    const float* prev_active     = (const float*)d_in[3];
    float* out = (float*)d_out;

    tm_active_kernel<<<4, 256>>>(active_columns, predictive, out);
    tm_row_kernel<<<NCELLS + 1, 256>>>(segment_weights, active_columns,
                                       predictive, prev_active, out);
}

// round 4
// speedup vs baseline: 1.2733x; 1.0779x over previous
#include <cuda_runtime.h>
#include <cuda_bf16.h>
#include <stdint.h>

#define COLS 1024
#define CPC 8
#define NCELLS 8192            // COLS * CPC
#define THRESH 13.0f
#define PERM_CONN 0.5f

// out layout: [0:8192) new_active, [8192:16384) new_predictive,
//             [16384] anomaly, [16385:16385+64M) new_segment_weights
//
// prev_has gate is algebraically removed: prev_active is binary >= 0, so
// (sum(prev)>0 && prev[r]!=0) == (prev[r]!=0), and when prev[r]==0 the
// updated row equals W anyway (clip is identity on [0,1)).

// ---------------------------------------------------------------------------
// K1: new_active (blocks 0..3, one thread per column) + anomaly (block 4).
// ---------------------------------------------------------------------------
__global__ __launch_bounds__(256) void tm_prep_kernel(
    const float* __restrict__ active_columns,
    const float* __restrict__ predictive_cells,
    float* __restrict__ out) {
    const int b = blockIdx.x;
    const int t = threadIdx.x;
    const float4* __restrict__ p4 = reinterpret_cast<const float4*>(predictive_cells);

    if (b < 4) {
        int c = b * 256 + t;                 // column id 0..1023
        float4 p0 = p4[2 * c];
        float4 p1 = p4[2 * c + 1];
        float psum = p0.x + p0.y + p0.z + p0.w + p1.x + p1.y + p1.z + p1.w;
        bool hp = psum > 0.f;
        bool am = active_columns[c] > 0.f;

        float4 v0, v1;
        if (hp) { v0 = p0; v1 = p1; }
        else    { v0 = make_float4(1.f, 1.f, 1.f, 1.f); v1 = v0; }
        if (!am) { v0 = make_float4(0.f, 0.f, 0.f, 0.f); v1 = v0; }
        float4* __restrict__ o4 = reinterpret_cast<float4*>(out);
        o4[2 * c]     = v0;
        o4[2 * c + 1] = v1;
    } else {
        // ---- anomaly ----
        float na = 0.f, np = 0.f;
#pragma unroll
        for (int k = 0; k < 4; k++) {
            int c = t + k * 256;
            float4 p0 = p4[2 * c];
            float4 p1 = p4[2 * c + 1];
            float psum = p0.x + p0.y + p0.z + p0.w + p1.x + p1.y + p1.z + p1.w;
            bool hp = psum > 0.f;
            bool am = active_columns[c] > 0.f;
            na += am ? 1.f : 0.f;
            np += (am && hp) ? 1.f : 0.f;
        }
#pragma unroll
        for (int off = 16; off > 0; off >>= 1) {
            na += __shfl_down_sync(0xFFFFFFFFu, na, off);
            np += __shfl_down_sync(0xFFFFFFFFu, np, off);
        }
        __shared__ float s_na[8], s_np[8];
        int w = t >> 5, l = t & 31;
        if (l == 0) { s_na[w] = na; s_np[w] = np; }
        __syncthreads();
        if (t == 0) {
            float tna = 0.f, tnp = 0.f;
#pragma unroll
            for (int i = 0; i < 8; i++) { tna += s_na[i]; tnp += s_np[i]; }
            out[2 * NCELLS] = 1.0f - tnp / fmaxf(tna, 1.0f);
        }
    }
}

// ---------------------------------------------------------------------------
// K2: R1's streaming row kernel, verbatim. One block per row, 256 threads,
// 8x float4 loads, scalar stores (output offset 16385 is 4B-aligned only).
// __launch_bounds__(256, 8) pins regs <= 32 -> 8 blocks/SM -> max MLP.
// ---------------------------------------------------------------------------
__global__ __launch_bounds__(256, 8) void tm_row_kernel(
    const float* __restrict__ W,
    const float* __restrict__ prev_active,
    float* __restrict__ out) {
    const int r = blockIdx.x;
    const int t = threadIdx.x;

    const float* __restrict__ a = out;                 // new_active
    float* __restrict__ pred_out = out + NCELLS;
    float* __restrict__ w_out = out + 2 * NCELLS + 1;  // offset 16385

    const float4* __restrict__ wrow =
        reinterpret_cast<const float4*>(W + (size_t)r * NCELLS);
    const float4* __restrict__ a4p = reinterpret_cast<const float4*>(a);
    float* __restrict__ orow = w_out + (size_t)r * NCELLS;

    const float p = prev_active[r];
    float acc = 0.f;

    if (p != 0.f) {
#pragma unroll
        for (int i = 0; i < 8; i++) {
            int idx = t + i * 256;
            float4 w4 = wrow[idx];
            float4 a4 = a4p[idx];
            acc += (w4.x >= PERM_CONN ? a4.x : 0.f)
                 + (w4.y >= PERM_CONN ? a4.y : 0.f)
                 + (w4.z >= PERM_CONN ? a4.z : 0.f)
                 + (w4.w >= PERM_CONN ? a4.w : 0.f);
            float ox = fminf(fmaxf(w4.x + (0.1f * a4.x - 0.01f * (1.f - a4.x)) * p, 0.f), 1.f);
            float oy = fminf(fmaxf(w4.y + (0.1f * a4.y - 0.01f * (1.f - a4.y)) * p, 0.f), 1.f);
            float oz = fminf(fmaxf(w4.z + (0.1f * a4.z - 0.01f * (1.f - a4.z)) * p, 0.f), 1.f);
            float ow = fminf(fmaxf(w4.w + (0.1f * a4.w - 0.01f * (1.f - a4.w)) * p, 0.f), 1.f);
            int j = idx * 4;
            orow[j + 0] = ox;
            orow[j + 1] = oy;
            orow[j + 2] = oz;
            orow[j + 3] = ow;
        }
    } else {
#pragma unroll
        for (int i = 0; i < 8; i++) {
            int idx = t + i * 256;
            float4 w4 = wrow[idx];
            float4 a4 = a4p[idx];
            acc += (w4.x >= PERM_CONN ? a4.x : 0.f)
                 + (w4.y >= PERM_CONN ? a4.y : 0.f)
                 + (w4.z >= PERM_CONN ? a4.z : 0.f)
                 + (w4.w >= PERM_CONN ? a4.w : 0.f);
            int j = idx * 4;
            orow[j + 0] = w4.x;
            orow[j + 1] = w4.y;
            orow[j + 2] = w4.z;
            orow[j + 3] = w4.w;
        }
    }

    // block reduction of acc -> presyn[r]
#pragma unroll
    for (int off = 16; off > 0; off >>= 1)
        acc += __shfl_down_sync(0xFFFFFFFFu, acc, off);
    __shared__ float sacc[8];
    int w = t >> 5, l = t & 31;
    if (l == 0) sacc[w] = acc;
    __syncthreads();
    if (t == 0) {
        float s = 0.f;
#pragma unroll
        for (int i = 0; i < 8; i++) s += sacc[i];
        pred_out[r] = (s >= THRESH) ? 1.0f : 0.0f;
    }
}

extern "C" void kernel_launch(void* const* d_in, const int* in_sizes, int n_in,
                              void* d_out, int out_size) {
    const float* active_columns  = (const float*)d_in[0];
    const float* segment_weights = (const float*)d_in[1];
    const float* predictive      = (const float*)d_in[2];
    const float* prev_active     = (const float*)d_in[3];
    float* out = (float*)d_out;

    tm_prep_kernel<<<5, 256>>>(active_columns, predictive, out);
    tm_row_kernel<<<NCELLS, 256>>>(segment_weights, prev_active, out);
}

// round 9
// speedup vs baseline: 1.2761x; 1.0022x over previous
#include <cuda_runtime.h>
#include <cuda_bf16.h>
#include <stdint.h>

#define COLS 1024
#define CPC 8
#define NCELLS 8192            // COLS * CPC
#define THRESH 13.0f
#define PERM_CONN 0.5f
#define NPREP 4                // blocks computing new_active

// out layout: [0:8192) new_active, [8192:16384) new_predictive,
//             [16384] anomaly, [16385:16385+64M) new_segment_weights
//
// prev_has gate is algebraically removed: prev_active is binary >= 0, so
// (sum(prev)>0 && prev[r]!=0) == (prev[r]!=0), and when prev[r]==0 the
// updated row equals W anyway (clip is identity on [0,1)).

__device__ int g_ready;   // set to NPREP once new_active is published
__device__ int g_done;    // row-block completion counter (self-resets)

__global__ __launch_bounds__(256, 8) void tm_fused_kernel(
    const float* __restrict__ W,
    const float* __restrict__ active_columns,
    const float* __restrict__ predictive_cells,
    const float* __restrict__ prev_active,
    float* __restrict__ out) {
    const int b = blockIdx.x;
    const int t = threadIdx.x;

    if (b < NPREP) {
        // ---- new_active: one thread per column ----
        const float4* __restrict__ p4 =
            reinterpret_cast<const float4*>(predictive_cells);
        int c = b * 256 + t;                 // column id 0..1023
        float4 p0 = p4[2 * c];
        float4 p1 = p4[2 * c + 1];
        float psum = p0.x + p0.y + p0.z + p0.w + p1.x + p1.y + p1.z + p1.w;
        bool hp = psum > 0.f;
        bool am = active_columns[c] > 0.f;

        float4 v0, v1;
        if (hp) { v0 = p0; v1 = p1; }
        else    { v0 = make_float4(1.f, 1.f, 1.f, 1.f); v1 = v0; }
        if (!am) { v0 = make_float4(0.f, 0.f, 0.f, 0.f); v1 = v0; }
        float4* __restrict__ o4 = reinterpret_cast<float4*>(out);
        o4[2 * c]     = v0;
        o4[2 * c + 1] = v1;

        __threadfence();                 // publish a before the flag
        __syncthreads();
        if (t == 0) atomicAdd(&g_ready, 1);
        return;
    }

    if (b == NPREP) {
        // ---- anomaly (nothing depends on it; runs concurrently) ----
        const float4* __restrict__ p4 =
            reinterpret_cast<const float4*>(predictive_cells);
        float na = 0.f, np = 0.f;
#pragma unroll
        for (int k = 0; k < 4; k++) {
            int c = t + k * 256;
            float4 p0 = p4[2 * c];
            float4 p1 = p4[2 * c + 1];
            float psum = p0.x + p0.y + p0.z + p0.w + p1.x + p1.y + p1.z + p1.w;
            bool hp = psum > 0.f;
            bool am = active_columns[c] > 0.f;
            na += am ? 1.f : 0.f;
            np += (am && hp) ? 1.f : 0.f;
        }
#pragma unroll
        for (int off = 16; off > 0; off >>= 1) {
            na += __shfl_down_sync(0xFFFFFFFFu, na, off);
            np += __shfl_down_sync(0xFFFFFFFFu, np, off);
        }
        __shared__ float s_na[8], s_np[8];
        int w = t >> 5, l = t & 31;
        if (l == 0) { s_na[w] = na; s_np[w] = np; }
        __syncthreads();
        if (t == 0) {
            float tna = 0.f, tnp = 0.f;
#pragma unroll
            for (int i = 0; i < 8; i++) { tna += s_na[i]; tnp += s_np[i]; }
            out[2 * NCELLS] = 1.0f - tnp / fmaxf(tna, 1.0f);
        }
        return;
    }

    // ---- row block: wait for new_active, then stream one 32KB row ----
    const int r = b - (NPREP + 1);

    if (t == 0) {
        while (__ldcg(&g_ready) < NPREP) __nanosleep(64);
    }
    __syncthreads();

    const float* __restrict__ a = out;                 // new_active
    float* __restrict__ pred_out = out + NCELLS;
    float* __restrict__ w_out = out + 2 * NCELLS + 1;  // offset 16385

    const float4* __restrict__ wrow =
        reinterpret_cast<const float4*>(W + (size_t)r * NCELLS);
    const float4* __restrict__ a4p = reinterpret_cast<const float4*>(a);
    float* __restrict__ orow = w_out + (size_t)r * NCELLS;

    const float p = prev_active[r];
    float acc = 0.f;

    if (p != 0.f) {
#pragma unroll
        for (int i = 0; i < 8; i++) {
            int idx = t + i * 256;
            float4 w4 = wrow[idx];
            float4 a4 = a4p[idx];
            acc += (w4.x >= PERM_CONN ? a4.x : 0.f)
                 + (w4.y >= PERM_CONN ? a4.y : 0.f)
                 + (w4.z >= PERM_CONN ? a4.z : 0.f)
                 + (w4.w >= PERM_CONN ? a4.w : 0.f);
            float ox = fminf(fmaxf(w4.x + (0.1f * a4.x - 0.01f * (1.f - a4.x)) * p, 0.f), 1.f);
            float oy = fminf(fmaxf(w4.y + (0.1f * a4.y - 0.01f * (1.f - a4.y)) * p, 0.f), 1.f);
            float oz = fminf(fmaxf(w4.z + (0.1f * a4.z - 0.01f * (1.f - a4.z)) * p, 0.f), 1.f);
            float ow = fminf(fmaxf(w4.w + (0.1f * a4.w - 0.01f * (1.f - a4.w)) * p, 0.f), 1.f);
            int j = idx * 4;
            orow[j + 0] = ox;
            orow[j + 1] = oy;
            orow[j + 2] = oz;
            orow[j + 3] = ow;
        }
    } else {
#pragma unroll
        for (int i = 0; i < 8; i++) {
            int idx = t + i * 256;
            float4 w4 = wrow[idx];
            float4 a4 = a4p[idx];
            acc += (w4.x >= PERM_CONN ? a4.x : 0.f)
                 + (w4.y >= PERM_CONN ? a4.y : 0.f)
                 + (w4.z >= PERM_CONN ? a4.z : 0.f)
                 + (w4.w >= PERM_CONN ? a4.w : 0.f);
            int j = idx * 4;
            orow[j + 0] = w4.x;
            orow[j + 1] = w4.y;
            orow[j + 2] = w4.z;
            orow[j + 3] = w4.w;
        }
    }

    // block reduction of acc -> new_predictive[r]
#pragma unroll
    for (int off = 16; off > 0; off >>= 1)
        acc += __shfl_down_sync(0xFFFFFFFFu, acc, off);
    __shared__ float sacc[8];
    int w = t >> 5, l = t & 31;
    if (l == 0) sacc[w] = acc;
    __syncthreads();
    if (t == 0) {
        float s = 0.f;
#pragma unroll
        for (int i = 0; i < 8; i++) s += sacc[i];
        pred_out[r] = (s >= THRESH) ? 1.0f : 0.0f;

        // ---- replay-safe self-reset: last row block zeroes the flags ----
        int v = atomicAdd(&g_done, 1);
        if (v == NCELLS - 1) {
            g_done = 0;
            g_ready = 0;
            __threadfence();
        }
    }
}

extern "C" void kernel_launch(void* const* d_in, const int* in_sizes, int n_in,
                              void* d_out, int out_size) {
    const float* active_columns  = (const float*)d_in[0];
    const float* segment_weights = (const float*)d_in[1];
    const float* predictive      = (const float*)d_in[2];
    const float* prev_active     = (const float*)d_in[3];
    float* out = (float*)d_out;

    tm_fused_kernel<<<NCELLS + NPREP + 1, 256>>>(
        segment_weights, active_columns, predictive, prev_active, out);
}